// round 1
// baseline (speedup 1.0000x reference)
#include <cuda_runtime.h>
#include <cuda_bf16.h>
#include <cstdint>

// Scratch for the reduction result (no allocations allowed).
__device__ float g_xmax;

// ---------------------------------------------------------------------------
// Kernel 1: max over x (n = 8192). Single CTA, warp-shuffle reduction.
// ---------------------------------------------------------------------------
__global__ void max_kernel(const float* __restrict__ x, int n) {
    __shared__ float smax[32];
    int tid = threadIdx.x;
    float m = 0.0f;  // x ~ uniform(0,1), nonnegative; 0 is a safe identity
    for (int i = tid; i < n; i += blockDim.x) {
        m = fmaxf(m, x[i]);
    }
    // warp reduce
    #pragma unroll
    for (int off = 16; off > 0; off >>= 1)
        m = fmaxf(m, __shfl_xor_sync(0xFFFFFFFFu, m, off));
    int warp = tid >> 5;
    int lane = tid & 31;
    if (lane == 0) smax[warp] = m;
    __syncthreads();
    if (warp == 0) {
        int nwarps = blockDim.x >> 5;
        m = (lane < nwarps) ? smax[lane] : 0.0f;
        #pragma unroll
        for (int off = 16; off > 0; off >>= 1)
            m = fmaxf(m, __shfl_xor_sync(0xFFFFFFFFu, m, off));
        if (lane == 0) g_xmax = m;
    }
}

// ---------------------------------------------------------------------------
// Kernel 2: out[0, j] = (floor(x[j]/max * 255) == t) ? weight[0, j] : 0
// Only the first in_features elements; rest of d_out already zeroed by memset.
// ---------------------------------------------------------------------------
__global__ void row0_kernel(const float* __restrict__ x,
                            const float* __restrict__ w,
                            const int* __restrict__ t_ptr,
                            float* __restrict__ out, int n) {
    int i = blockIdx.x * blockDim.x + threadIdx.x;
    if (i < n) {
        const int t = *t_ptr;
        float xn = (x[i] / g_xmax) * 255.0f;   // same op order as reference
        int q = (int)floorf(xn);
        out[i] = (q == t) ? w[i] : 0.0f;
    }
}

extern "C" void kernel_launch(void* const* d_in, const int* in_sizes, int n_in,
                              void* d_out, int out_size) {
    const float* x = (const float*)d_in[0];        // (1, 8192)
    const float* w = (const float*)d_in[1];        // (4096, 8192)
    const int*   t = (const int*)d_in[2];          // scalar
    float* out = (float*)d_out;

    const int in_features = in_sizes[0];           // 8192

    // Zero the entire output (poisoned to 0xAA); the memset engine path
    // saturates HBM write bandwidth. Row 0 is overwritten afterwards in
    // stream order.
    cudaMemsetAsync(d_out, 0, (size_t)out_size * sizeof(float), 0);

    max_kernel<<<1, 1024>>>(x, in_features);

    int threads = 256;
    int blocks = (in_features + threads - 1) / threads;
    row0_kernel<<<blocks, threads>>>(x, w, t, out, in_features);
}

// round 2
// speedup vs baseline: 1.1444x; 1.1444x over previous
#include <cuda_runtime.h>
#include <cuda_bf16.h>
#include <cstdint>

// ---------------------------------------------------------------------------
// Single fused kernel:
//   block 0      : max-reduce x (8192 floats), then write row 0 masked.
//   blocks 1..B-1: zero rows 1..4095 of the output with float4 stores.
// Output rows >= 1 are always zero in the reference (spikes only on row 0),
// and d_out is poisoned, so the full 128 MiB must be written. This kernel is
// pure HBM-write-bound; everything else is noise.
// ---------------------------------------------------------------------------
__global__ void fused_kernel(const float4* __restrict__ x4,
                             const float4* __restrict__ w4,
                             const int* __restrict__ t_ptr,
                             float4* __restrict__ out4,
                             int row0_vec,     // in_features / 4
                             long long total_vec) // out_size / 4
{
    const int tid = threadIdx.x;

    if (blockIdx.x == 0) {
        // ---- max reduction over x (exact fp32, matches jnp.max) ----
        __shared__ float smax[32];
        float m = 0.0f;  // x ~ U(0,1), nonnegative
        for (int j = tid; j < row0_vec; j += blockDim.x) {
            float4 v = x4[j];
            m = fmaxf(m, fmaxf(fmaxf(v.x, v.y), fmaxf(v.z, v.w)));
        }
        #pragma unroll
        for (int off = 16; off > 0; off >>= 1)
            m = fmaxf(m, __shfl_xor_sync(0xFFFFFFFFu, m, off));
        const int warp = tid >> 5, lane = tid & 31;
        if (lane == 0) smax[warp] = m;
        __syncthreads();
        if (warp == 0) {
            int nwarps = blockDim.x >> 5;
            m = (lane < nwarps) ? smax[lane] : 0.0f;
            #pragma unroll
            for (int off = 16; off > 0; off >>= 1)
                m = fmaxf(m, __shfl_xor_sync(0xFFFFFFFFu, m, off));
            if (lane == 0) smax[0] = m;
        }
        __syncthreads();
        const float xmax = smax[0];
        const int t = *t_ptr;

        // ---- row 0: out[0,j] = (floor(x[j]/xmax*255) == t) ? w[0,j] : 0 ----
        for (int j = tid; j < row0_vec; j += blockDim.x) {
            float4 xv = x4[j];
            float4 wv = w4[j];
            float4 o;
            o.x = ((int)floorf(xv.x / xmax * 255.0f) == t) ? wv.x : 0.0f;
            o.y = ((int)floorf(xv.y / xmax * 255.0f) == t) ? wv.y : 0.0f;
            o.z = ((int)floorf(xv.z / xmax * 255.0f) == t) ? wv.z : 0.0f;
            o.w = ((int)floorf(xv.w / xmax * 255.0f) == t) ? wv.w : 0.0f;
            out4[j] = o;
        }
    } else {
        // ---- zero rows 1..end with wide stores ----
        const float4 z = make_float4(0.0f, 0.0f, 0.0f, 0.0f);
        const long long stride = (long long)(gridDim.x - 1) * blockDim.x;
        long long i = (long long)row0_vec +
                      (long long)(blockIdx.x - 1) * blockDim.x + tid;
        for (; i < total_vec; i += stride)
            out4[i] = z;
    }
}

extern "C" void kernel_launch(void* const* d_in, const int* in_sizes, int n_in,
                              void* d_out, int out_size) {
    const float4* x4 = (const float4*)d_in[0];   // (1, 8192)
    const float4* w4 = (const float4*)d_in[1];   // (4096, 8192), row 0 only used
    const int*    t  = (const int*)d_in[2];      // scalar
    float4* out4 = (float4*)d_out;

    const int in_features = in_sizes[0];         // 8192
    const int row0_vec = in_features / 4;        // 2048
    const long long total_vec = (long long)out_size / 4;

    // 1 max/row0 block + enough zeroing blocks to saturate HBM write BW.
    // 148 SMs; give each SM ~8 CTAs of 256 threads for full store pipelining.
    const int blocks = 1 + 148 * 8;
    fused_kernel<<<blocks, 256>>>(x4, w4, t, out4, row0_vec, total_vec);
}

// round 3
// speedup vs baseline: 1.1747x; 1.0265x over previous
#include <cuda_runtime.h>
#include <cuda_bf16.h>
#include <cstdint>

// ---------------------------------------------------------------------------
// Single fused kernel, pure HBM-write-bound:
//   block 0      : max-reduce x (8192 floats), then write row 0 masked.
//   blocks 1..B-1: zero rows 1..4095 with streaming (evict-first) float4
//                  stores, 8 independent stores in flight per iteration.
// ---------------------------------------------------------------------------

#define ZERO_BLOCKS (148 * 8)       // full-occupancy zero grid (8 CTAs/SM)
#define ZTHREADS    256
#define UNROLL      8               // independent STG.128 per iteration

__global__ void __launch_bounds__(ZTHREADS)
fused_kernel(const float4* __restrict__ x4,
             const float4* __restrict__ w4,
             const int* __restrict__ t_ptr,
             float4* __restrict__ out4,
             int row0_vec,            // in_features / 4
             long long total_vec)     // out_size / 4
{
    const int tid = threadIdx.x;

    if (blockIdx.x == 0) {
        // ---- max reduction over x (exact fp32, matches jnp.max) ----
        __shared__ float smax[32];
        float m = 0.0f;  // x ~ U(0,1), nonnegative
        for (int j = tid; j < row0_vec; j += blockDim.x) {
            float4 v = x4[j];
            m = fmaxf(m, fmaxf(fmaxf(v.x, v.y), fmaxf(v.z, v.w)));
        }
        #pragma unroll
        for (int off = 16; off > 0; off >>= 1)
            m = fmaxf(m, __shfl_xor_sync(0xFFFFFFFFu, m, off));
        const int warp = tid >> 5, lane = tid & 31;
        if (lane == 0) smax[warp] = m;
        __syncthreads();
        if (warp == 0) {
            int nwarps = blockDim.x >> 5;
            m = (lane < nwarps) ? smax[lane] : 0.0f;
            #pragma unroll
            for (int off = 16; off > 0; off >>= 1)
                m = fmaxf(m, __shfl_xor_sync(0xFFFFFFFFu, m, off));
            if (lane == 0) smax[0] = m;
        }
        __syncthreads();
        const float xmax = smax[0];
        const int t = *t_ptr;

        // ---- row 0: out[0,j] = (floor(x[j]/xmax*255) == t) ? w[0,j] : 0 ----
        for (int j = tid; j < row0_vec; j += blockDim.x) {
            float4 xv = x4[j];
            float4 wv = w4[j];
            float4 o;
            o.x = ((int)floorf(xv.x / xmax * 255.0f) == t) ? wv.x : 0.0f;
            o.y = ((int)floorf(xv.y / xmax * 255.0f) == t) ? wv.y : 0.0f;
            o.z = ((int)floorf(xv.z / xmax * 255.0f) == t) ? wv.z : 0.0f;
            o.w = ((int)floorf(xv.w / xmax * 255.0f) == t) ? wv.w : 0.0f;
            out4[j] = o;
        }
    } else {
        // ---- zero rows 1..end: streaming stores, 8-deep MLP ----
        const float4 z = make_float4(0.0f, 0.0f, 0.0f, 0.0f);
        const long long zero_vec = total_vec - row0_vec;
        float4* base = out4 + row0_vec;

        const long long nthreads   = (long long)ZERO_BLOCKS * ZTHREADS;
        const long long chunk      = nthreads * UNROLL;       // vec4 per outer iter
        const long long full_iters = zero_vec / chunk;

        // Block-contiguous layout: CTA b covers [b*ZTHREADS*UNROLL, ...)
        // within each chunk; the UNROLL stores of one thread are strided by
        // ZTHREADS so every store instruction is fully coalesced warp-wide.
        long long my = (long long)(blockIdx.x - 1) * (ZTHREADS * UNROLL) + tid;

        for (long long it = 0; it < full_iters; ++it) {
            float4* p = base + my + it * chunk;
            #pragma unroll
            for (int k = 0; k < UNROLL; ++k)
                __stcs(p + (long long)k * ZTHREADS, z);
        }

        // Tail: whatever remains after the full chunks.
        long long done = full_iters * chunk;
        for (long long i = done + (long long)(blockIdx.x - 1) * ZTHREADS + tid;
             i < zero_vec;
             i += (long long)ZERO_BLOCKS * ZTHREADS)
            __stcs(base + i, z);
    }
}

extern "C" void kernel_launch(void* const* d_in, const int* in_sizes, int n_in,
                              void* d_out, int out_size) {
    const float4* x4 = (const float4*)d_in[0];   // (1, 8192)
    const float4* w4 = (const float4*)d_in[1];   // (4096, 8192), row 0 only used
    const int*    t  = (const int*)d_in[2];      // scalar
    float4* out4 = (float4*)d_out;

    const int in_features = in_sizes[0];         // 8192
    const int row0_vec = in_features / 4;        // 2048
    const long long total_vec = (long long)out_size / 4;

    fused_kernel<<<1 + ZERO_BLOCKS, ZTHREADS>>>(x4, w4, t, out4,
                                                row0_vec, total_vec);
}